// round 8
// baseline (speedup 1.0000x reference)
#include <cuda_runtime.h>
#include <math.h>
#include <stdint.h>

#define BB 8
#define TT 2048
#define CC 384
#define HH 64
#define NTOK (BB * TT)   // 16384

__device__ uint32_t g_qkv[3 * NTOK * HH];         // q | k | v, tf32 bits
__device__ float g_Z[NTOK];                       // per-(b,s) column sum of exp

__device__ __forceinline__ uint32_t f2tf(float f) {
    uint32_t r; asm("cvt.rna.tf32.f32 %0, %1;" : "=r"(r) : "f"(f)); return r;
}
__device__ __forceinline__ float frcp(float f) {
    float r; asm("rcp.approx.f32 %0, %1;" : "=f"(r) : "f"(f)); return r;
}
__device__ __forceinline__ void mma8(float* c, const uint32_t* a, const uint32_t* b) {
    asm volatile(
        "mma.sync.aligned.m16n8k8.row.col.f32.tf32.tf32.f32 "
        "{%0,%1,%2,%3}, {%4,%5,%6,%7}, {%8,%9}, {%0,%1,%2,%3};\n"
        : "+f"(c[0]), "+f"(c[1]), "+f"(c[2]), "+f"(c[3])
        : "r"(a[0]), "r"(a[1]), "r"(a[2]), "r"(a[3]), "r"(b[0]), "r"(b[1]));
}
__device__ __forceinline__ void cpa16(uint32_t s, const void* g) {
    asm volatile("cp.async.cg.shared.global [%0], [%1], 16;" :: "r"(s), "l"(g));
}
__device__ __forceinline__ void cp_commit() { asm volatile("cp.async.commit_group;"); }
template<int N> __device__ __forceinline__ void cp_wait() {
    asm volatile("cp.async.wait_group %0;" :: "n"(N));
}

// ---------------------------------------------------------------------------
// Kernel A: fused QKV projection. grid(256), 256 thr (8 warps), 2 CTAs/SM.
// Block computes 64 rows x (q,k,v). Warps 2(m) x 4(n): 32x16 per output.
// Also zeroes g_Z.
// ---------------------------------------------------------------------------
__global__ void __launch_bounds__(256, 2) qkv_kernel(
        const float* __restrict__ x,
        const float* __restrict__ Wq,
        const float* __restrict__ Wk,
        const float* __restrict__ Wv) {
    __shared__ float Xs[2][64][36];       // pad 36 (==4 mod 32)
    __shared__ float Ws[2][3][32][72];    // pad 72 (==8 mod 32)
    const uint32_t XB = (uint32_t)__cvta_generic_to_shared(&Xs[0][0][0]);
    const uint32_t WB = (uint32_t)__cvta_generic_to_shared(&Ws[0][0][0][0]);
    const float* Wmat[3] = {Wq, Wk, Wv};

    const int r0  = blockIdx.x * 64;
    const int tid = threadIdx.x, lane = tid & 31, wid = tid >> 5;
    const int lr = lane >> 2, lc = lane & 3;
    const int wm = (wid >> 2) * 32, wn = (wid & 3) * 16;

    if (tid < 64) g_Z[blockIdx.x * 64 + tid] = 0.f;

    for (int i = tid; i < 512; i += 256) {            // X 64x32
        int r = i >> 3, c4 = i & 7;
        cpa16(XB + (r * 36 + c4 * 4) * 4, x + (size_t)(r0 + r) * CC + c4 * 4);
    }
    for (int i = tid; i < 1536; i += 256) {           // W 3x32x64
        int w = i >> 9, j = i & 511, r = j >> 4, c4 = j & 15;
        cpa16(WB + ((w * 32 + r) * 72 + c4 * 4) * 4, Wmat[w] + (size_t)r * HH + c4 * 4);
    }
    cp_commit();

    float acc[3][2][2][4] = {};
    for (int k0 = 0; k0 < CC; k0 += 32) {
        const int st = (k0 >> 5) & 1;
        if (k0 + 32 < CC) {
            const uint32_t xD = XB + (st ^ 1) * 64 * 36 * 4;
            const uint32_t wD = WB + (st ^ 1) * 3 * 32 * 72 * 4;
            for (int i = tid; i < 512; i += 256) {
                int r = i >> 3, c4 = i & 7;
                cpa16(xD + (r * 36 + c4 * 4) * 4,
                      x + (size_t)(r0 + r) * CC + k0 + 32 + c4 * 4);
            }
            for (int i = tid; i < 1536; i += 256) {
                int w = i >> 9, j = i & 511, r = j >> 4, c4 = j & 15;
                cpa16(wD + ((w * 32 + r) * 72 + c4 * 4) * 4,
                      Wmat[w] + (size_t)(k0 + 32 + r) * HH + c4 * 4);
            }
            cp_commit();
            cp_wait<1>();
        } else {
            cp_wait<0>();
        }
        __syncthreads();

        #pragma unroll
        for (int ks = 0; ks < 4; ks++) {
            const int k = ks * 8;
            uint32_t a[2][4];
            #pragma unroll
            for (int mi = 0; mi < 2; mi++) {
                int rb = wm + mi * 16;
                a[mi][0] = f2tf(Xs[st][rb + lr][k + lc]);
                a[mi][1] = f2tf(Xs[st][rb + lr + 8][k + lc]);
                a[mi][2] = f2tf(Xs[st][rb + lr][k + lc + 4]);
                a[mi][3] = f2tf(Xs[st][rb + lr + 8][k + lc + 4]);
            }
            #pragma unroll
            for (int w = 0; w < 3; w++) {
                uint32_t bf[2][2];
                #pragma unroll
                for (int ni = 0; ni < 2; ni++) {
                    int cb = wn + ni * 8 + lr;
                    bf[ni][0] = f2tf(Ws[st][w][k + lc][cb]);
                    bf[ni][1] = f2tf(Ws[st][w][k + lc + 4][cb]);
                }
                #pragma unroll
                for (int mi = 0; mi < 2; mi++)
                    #pragma unroll
                    for (int ni = 0; ni < 2; ni++)
                        mma8(acc[w][mi][ni], a[mi], bf[ni]);
            }
        }
        __syncthreads();
    }

    #pragma unroll
    for (int w = 0; w < 3; w++) {
        uint32_t* dst = &g_qkv[(size_t)w * NTOK * HH];
        #pragma unroll
        for (int mi = 0; mi < 2; mi++)
            #pragma unroll
            for (int ni = 0; ni < 2; ni++) {
                int row = r0 + wm + mi * 16 + lr;
                int col = wn + ni * 8 + 2 * lc;
                *(uint2*)&dst[(size_t)row * HH + col] =
                    make_uint2(f2tf(acc[w][mi][ni][0]), f2tf(acc[w][mi][ni][1]));
                *(uint2*)&dst[(size_t)(row + 8) * HH + col] =
                    make_uint2(f2tf(acc[w][mi][ni][2]), f2tf(acc[w][mi][ni][3]));
            }
    }
}

// ---------------------------------------------------------------------------
// Kernel B: Z[s] = sum_{t>=s} exp(scale*q_t.k_s). cp.async double-buffered Q.
// grid(16 s-tiles, 4 t-chunks, B), 256 thr, K tile persistent.
// ---------------------------------------------------------------------------
__global__ void __launch_bounds__(256, 2) stats_kernel() {
    extern __shared__ uint32_t sm_[];
    uint32_t (*Ks)[68]      = (uint32_t(*)[68])sm_;
    uint32_t (*Qs)[128][68] = (uint32_t(*)[128][68])(sm_ + 128 * 68);
    const uint32_t sbase = (uint32_t)__cvta_generic_to_shared(sm_);
    const uint32_t KS_B = sbase, QS_B = sbase + 128 * 68 * 4;

    const int si = blockIdx.x, c = blockIdx.y, b = blockIdx.z;
    const int tBeg = max(si, c * 4), tEnd = min(16, c * 4 + 4);
    if (tBeg >= tEnd) return;
    const int s0 = si * 128;
    const uint32_t* q  = &g_qkv[(size_t)b * TT * HH];
    const uint32_t* kp = &g_qkv[(size_t)(NTOK + b * TT) * HH];
    const int tid = threadIdx.x, lane = tid & 31, wid = tid >> 5;
    const int lr = lane >> 2, lc = lane & 3;
    const int wm = (wid >> 2) * 64, wn = (wid & 3) * 32;
    const float scale = rsqrtf((float)CC);

    for (int i = tid; i < 2048; i += 256) {
        int r = i >> 4, c4 = i & 15;
        cpa16(KS_B + (r * 68 + c4 * 4) * 4, kp + (size_t)(s0 + r) * HH + c4 * 4);
        cpa16(QS_B + (r * 68 + c4 * 4) * 4, q + (size_t)(tBeg * 128 + r) * HH + c4 * 4);
    }
    cp_commit();

    float colsum[4][2] = {};
    for (int ti = tBeg; ti < tEnd; ti++) {
        const int st = (ti - tBeg) & 1;
        if (ti + 1 < tEnd) {
            const uint32_t dstB = QS_B + (st ^ 1) * 128 * 68 * 4;
            for (int i = tid; i < 2048; i += 256) {
                int r = i >> 4, c4 = i & 15;
                cpa16(dstB + (r * 68 + c4 * 4) * 4,
                      q + (size_t)((ti + 1) * 128 + r) * HH + c4 * 4);
            }
            cp_commit();
            cp_wait<1>();
        } else {
            cp_wait<0>();
        }
        __syncthreads();

        const int t0 = ti * 128;
        float acc[4][4][4] = {};
        #pragma unroll
        for (int ks = 0; ks < 8; ks++) {
            const int k = ks * 8;
            uint32_t a[4][4], bf[4][2];
            #pragma unroll
            for (int mi = 0; mi < 4; mi++) {
                int rb = wm + mi * 16;
                a[mi][0] = Qs[st][rb + lr][k + lc];
                a[mi][1] = Qs[st][rb + lr + 8][k + lc];
                a[mi][2] = Qs[st][rb + lr][k + lc + 4];
                a[mi][3] = Qs[st][rb + lr + 8][k + lc + 4];
            }
            #pragma unroll
            for (int ni = 0; ni < 4; ni++) {
                int sb = wn + ni * 8 + lr;
                bf[ni][0] = Ks[sb][k + lc];
                bf[ni][1] = Ks[sb][k + lc + 4];
            }
            #pragma unroll
            for (int mi = 0; mi < 4; mi++)
                #pragma unroll
                for (int ni = 0; ni < 4; ni++)
                    mma8(acc[mi][ni], a[mi], bf[ni]);
        }

        #pragma unroll
        for (int mi = 0; mi < 4; mi++)
            #pragma unroll
            for (int ni = 0; ni < 4; ni++) {
                int tg = t0 + wm + mi * 16 + lr;
                int sg = s0 + wn + ni * 8 + 2 * lc;
                float e0 = (tg >= sg)         ? __expf(acc[mi][ni][0] * scale) : 0.f;
                float e1 = (tg >= sg + 1)     ? __expf(acc[mi][ni][1] * scale) : 0.f;
                float e2 = (tg + 8 >= sg)     ? __expf(acc[mi][ni][2] * scale) : 0.f;
                float e3 = (tg + 8 >= sg + 1) ? __expf(acc[mi][ni][3] * scale) : 0.f;
                colsum[ni][0] += e0 + e2;
                colsum[ni][1] += e1 + e3;
            }
        __syncthreads();
    }

    #pragma unroll
    for (int ni = 0; ni < 4; ni++)
        #pragma unroll
        for (int jj = 0; jj < 2; jj++) {
            float v = colsum[ni][jj];
            v += __shfl_xor_sync(0xffffffffu, v, 16);
            v += __shfl_xor_sync(0xffffffffu, v, 8);
            v += __shfl_xor_sync(0xffffffffu, v, 4);
            colsum[ni][jj] = v;
        }
    if (lr == 0) {
        #pragma unroll
        for (int ni = 0; ni < 4; ni++) {
            int sg = s0 + wn + ni * 8 + 2 * lc;
            atomicAdd(&g_Z[b * TT + sg],     colsum[ni][0]);
            atomicAdd(&g_Z[b * TT + sg + 1], colsum[ni][1]);
        }
    }
}

// ---------------------------------------------------------------------------
// Kernel C: v[s,:] *= 1/Z[s]  (in-place on tf32 bits). grid(1024), 256 thr.
// Each thread: one uint4 = 4 h of one (b,s) row.
// ---------------------------------------------------------------------------
__global__ void vscale_kernel() {
    const int i = blockIdx.x * 256 + threadIdx.x;     // uint4 index
    const int row = i >> 4;                           // 16 uint4 per row (64 h)
    const float rz = frcp(g_Z[row]);
    uint32_t* vp = &g_qkv[(size_t)2 * NTOK * HH];
    uint4 u = *(uint4*)&vp[(size_t)i * 4];
    u.x = f2tf(__uint_as_float(u.x) * rz);
    u.y = f2tf(__uint_as_float(u.y) * rz);
    u.z = f2tf(__uint_as_float(u.z) * rz);
    u.w = f2tf(__uint_as_float(u.w) * rz);
    *(uint4*)&vp[(size_t)i * 4] = u;
}

// ---------------------------------------------------------------------------
// Kernel D: fused recompute QK^T -> P=exp -> PV (V pre-scaled by 1/Z).
// Single-buffered K/V (2 CTAs/SM), K[s+1] prefetched during PV phase,
// V[s+1] during next QK. grid(8 s-chunks of 4x64, 16 t-tiles, B), 256 thr.
// smem words: Qs 0..8704, Ps ..17408, Ks ..21760, Vs ..26368 => 105472 B.
// ---------------------------------------------------------------------------
__global__ void __launch_bounds__(256, 2) pv_kernel(float* __restrict__ out) {
    extern __shared__ uint32_t sm_[];
    uint32_t (*Qs)[68] = (uint32_t(*)[68])sm_;                 // 128x64
    uint32_t (*Ps)[68] = (uint32_t(*)[68])(sm_ + 8704);        // 128x64
    uint32_t (*Ks)[68] = (uint32_t(*)[68])(sm_ + 17408);       // 64x64
    uint32_t (*Vs)[72] = (uint32_t(*)[72])(sm_ + 21760);       // 64x64
    const uint32_t sbase = (uint32_t)__cvta_generic_to_shared(sm_);
    const uint32_t QS_B = sbase, KS_B = sbase + 17408 * 4, VS_B = sbase + 21760 * 4;

    const int c = blockIdx.x, ti = blockIdx.y, b = blockIdx.z;
    const int sBeg = c * 4;
    const int sEnd = min(sBeg + 4, 2 * (ti + 1));
    if (sBeg >= sEnd) return;
    const int t0 = ti * 128;

    const uint32_t* q  = &g_qkv[(size_t)b * TT * HH];
    const uint32_t* kp = &g_qkv[(size_t)(NTOK + b * TT) * HH];
    const uint32_t* vp = &g_qkv[(size_t)(2 * NTOK + b * TT) * HH];
    const int tid = threadIdx.x, lane = tid & 31, wid = tid >> 5;
    const int lr = lane >> 2, lc = lane & 3;
    const float scale = rsqrtf((float)CC);
    const int wmq = (wid >> 2) * 64, wnq = (wid & 3) * 16;
    const int wm  = (wid >> 1) * 32, wn  = (wid & 1) * 32;

    for (int i = tid; i < 2048; i += 256) {
        int r = i >> 4, c4 = i & 15;
        cpa16(QS_B + (r * 68 + c4 * 4) * 4, q + (size_t)(t0 + r) * HH + c4 * 4);
    }
    {
        const int s0 = sBeg * 64;
        for (int i = tid; i < 1024; i += 256) {
            int r = i >> 4, c4 = i & 15;
            cpa16(KS_B + (r * 68 + c4 * 4) * 4, kp + (size_t)(s0 + r) * HH + c4 * 4);
            cpa16(VS_B + (r * 72 + c4 * 4) * 4, vp + (size_t)(s0 + r) * HH + c4 * 4);
        }
    }
    cp_commit();

    float acc_o[2][4][4] = {};

    for (int s64 = sBeg; s64 < sEnd; s64++) {
        cp_wait<0>();
        __syncthreads();

        const int s0 = s64 * 64;
        // --- QK^T: 128x64x64 ---
        float acc_qk[4][2][4] = {};
        #pragma unroll
        for (int ks = 0; ks < 8; ks++) {
            const int k = ks * 8;
            uint32_t a[4][4], bf[2][2];
            #pragma unroll
            for (int mi = 0; mi < 4; mi++) {
                int rb = wmq + mi * 16;
                a[mi][0] = Qs[rb + lr][k + lc];
                a[mi][1] = Qs[rb + lr + 8][k + lc];
                a[mi][2] = Qs[rb + lr][k + lc + 4];
                a[mi][3] = Qs[rb + lr + 8][k + lc + 4];
            }
            #pragma unroll
            for (int ni = 0; ni < 2; ni++) {
                int sb = wnq + ni * 8 + lr;
                bf[ni][0] = Ks[sb][k + lc];
                bf[ni][1] = Ks[sb][k + lc + 4];
            }
            #pragma unroll
            for (int mi = 0; mi < 4; mi++)
                #pragma unroll
                for (int ni = 0; ni < 2; ni++)
                    mma8(acc_qk[mi][ni], a[mi], bf[ni]);
        }

        // --- P = exp(S) -> smem (V already carries 1/Z) ---
        #pragma unroll
        for (int mi = 0; mi < 4; mi++)
            #pragma unroll
            for (int ni = 0; ni < 2; ni++) {
                int tr = wmq + mi * 16 + lr;
                int sc = wnq + ni * 8 + 2 * lc;
                int tg = t0 + tr, sg = s0 + sc;
                uint2 u;
                u.x = f2tf((tg >= sg)     ? __expf(acc_qk[mi][ni][0] * scale) : 0.f);
                u.y = f2tf((tg >= sg + 1) ? __expf(acc_qk[mi][ni][1] * scale) : 0.f);
                *(uint2*)&Ps[tr][sc] = u;
                u.x = f2tf((tg + 8 >= sg)     ? __expf(acc_qk[mi][ni][2] * scale) : 0.f);
                u.y = f2tf((tg + 8 >= sg + 1) ? __expf(acc_qk[mi][ni][3] * scale) : 0.f);
                *(uint2*)&Ps[tr + 8][sc] = u;
            }
        __syncthreads();   // K consumed, Ps visible

        if (s64 + 1 < sEnd) {       // prefetch K[s+1] over the PV phase
            const int s0n = (s64 + 1) * 64;
            for (int i = tid; i < 1024; i += 256) {
                int r = i >> 4, c4 = i & 15;
                cpa16(KS_B + (r * 68 + c4 * 4) * 4, kp + (size_t)(s0n + r) * HH + c4 * 4);
            }
            cp_commit();
        }

        // --- O += P(128x64) @ V(64x64) ---
        #pragma unroll
        for (int ks = 0; ks < 8; ks++) {
            const int k = ks * 8;
            uint32_t a[2][4], bf[4][2];
            #pragma unroll
            for (int mi = 0; mi < 2; mi++) {
                int rb = wm + mi * 16;
                a[mi][0] = Ps[rb + lr][k + lc];
                a[mi][1] = Ps[rb + lr + 8][k + lc];
                a[mi][2] = Ps[rb + lr][k + lc + 4];
                a[mi][3] = Ps[rb + lr + 8][k + lc + 4];
            }
            #pragma unroll
            for (int ni = 0; ni < 4; ni++) {
                int cb = wn + ni * 8 + lr;
                bf[ni][0] = Vs[k + lc][cb];
                bf[ni][1] = Vs[k + lc + 4][cb];
            }
            #pragma unroll
            for (int mi = 0; mi < 2; mi++)
                #pragma unroll
                for (int ni = 0; ni < 4; ni++)
                    mma8(acc_o[mi][ni], a[mi], bf[ni]);
        }
        __syncthreads();   // V consumed

        if (s64 + 1 < sEnd) {       // prefetch V[s+1]
            const int s0n = (s64 + 1) * 64;
            for (int i = tid; i < 1024; i += 256) {
                int r = i >> 4, c4 = i & 15;
                cpa16(VS_B + (r * 72 + c4 * 4) * 4, vp + (size_t)(s0n + r) * HH + c4 * 4);
            }
            cp_commit();
        }
    }

    #pragma unroll
    for (int mi = 0; mi < 2; mi++)
        #pragma unroll
        for (int ni = 0; ni < 4; ni++) {
            int row = b * TT + t0 + wm + mi * 16 + lr;
            int col = wn + ni * 8 + 2 * lc;
            float* o = &out[(size_t)row * HH + col];
            atomicAdd(o,     acc_o[mi][ni][0]);
            atomicAdd(o + 1, acc_o[mi][ni][1]);
            float* o2 = o + 8 * HH;
            atomicAdd(o2,     acc_o[mi][ni][2]);
            atomicAdd(o2 + 1, acc_o[mi][ni][3]);
        }
}

// ---------------------------------------------------------------------------
extern "C" void kernel_launch(void* const* d_in, const int* in_sizes, int n_in,
                              void* d_out, int out_size) {
    const float* x  = (const float*)d_in[0];
    const float* Wq = (const float*)d_in[1];
    const float* Wk = (const float*)d_in[2];
    const float* Wv = (const float*)d_in[3];
    float* out = (float*)d_out;

    const int stats_smem = (128 * 68 + 2 * 128 * 68) * 4;   // 104448
    const int pv_smem    = 26368 * 4;                       // 105472
    cudaFuncSetAttribute(stats_kernel, cudaFuncAttributeMaxDynamicSharedMemorySize, stats_smem);
    cudaFuncSetAttribute(pv_kernel,    cudaFuncAttributeMaxDynamicSharedMemorySize, pv_smem);

    cudaMemsetAsync(d_out, 0, (size_t)out_size * sizeof(float));
    qkv_kernel<<<256, 256>>>(x, Wq, Wk, Wv);
    stats_kernel<<<dim3(16, 4, BB), 256, stats_smem>>>();
    vscale_kernel<<<NTOK * HH / 1024, 256>>>();
    pv_kernel<<<dim3(8, 16, BB), 256, pv_smem>>>(out);
}

// round 9
// speedup vs baseline: 1.2831x; 1.2831x over previous
#include <cuda_runtime.h>
#include <cuda_fp16.h>
#include <math.h>
#include <stdint.h>

#define BB 8
#define TT 2048
#define CC 384
#define HH 64
#define HH2 32                      // half2 per row
#define NTOK (BB * TT)              // 16384

__device__ uint32_t g_qk[2 * NTOK * HH2];   // q | k, packed half2 [tok][h2]
__device__ __half   g_vT[(size_t)NTOK * HH];// v transposed: [(b*HH+h)*TT + t]
__device__ float    g_Z[NTOK];              // per-(b,s) column sum of exp

__device__ __forceinline__ uint32_t f2tf(float f) {
    uint32_t r; asm("cvt.rna.tf32.f32 %0, %1;" : "=r"(r) : "f"(f)); return r;
}
__device__ __forceinline__ uint32_t f2h2(float lo, float hi) {   // pack {lo,hi}
    uint32_t r; asm("cvt.rn.f16x2.f32 %0, %1, %2;" : "=r"(r) : "f"(hi), "f"(lo)); return r;
}
__device__ __forceinline__ float frcp(float f) {
    float r; asm("rcp.approx.f32 %0, %1;" : "=f"(r) : "f"(f)); return r;
}
__device__ __forceinline__ void mma8(float* c, const uint32_t* a, const uint32_t* b) {
    asm volatile(
        "mma.sync.aligned.m16n8k8.row.col.f32.tf32.tf32.f32 "
        "{%0,%1,%2,%3}, {%4,%5,%6,%7}, {%8,%9}, {%0,%1,%2,%3};\n"
        : "+f"(c[0]), "+f"(c[1]), "+f"(c[2]), "+f"(c[3])
        : "r"(a[0]), "r"(a[1]), "r"(a[2]), "r"(a[3]), "r"(b[0]), "r"(b[1]));
}
__device__ __forceinline__ void mma16(float* c, const uint32_t* a, const uint32_t* b) {
    asm volatile(
        "mma.sync.aligned.m16n8k16.row.col.f32.f16.f16.f32 "
        "{%0,%1,%2,%3}, {%4,%5,%6,%7}, {%8,%9}, {%0,%1,%2,%3};\n"
        : "+f"(c[0]), "+f"(c[1]), "+f"(c[2]), "+f"(c[3])
        : "r"(a[0]), "r"(a[1]), "r"(a[2]), "r"(a[3]), "r"(b[0]), "r"(b[1]));
}
__device__ __forceinline__ void cpa16(uint32_t s, const void* g) {
    asm volatile("cp.async.cg.shared.global [%0], [%1], 16;" :: "r"(s), "l"(g));
}
__device__ __forceinline__ void cp_commit() { asm volatile("cp.async.commit_group;"); }
template<int N> __device__ __forceinline__ void cp_wait() {
    asm volatile("cp.async.wait_group %0;" :: "n"(N));
}

// ---------------------------------------------------------------------------
// Kernel A: fused QKV projection (tf32 internals). grid(256), 256 thr.
// Epilogue: q,k as packed half2 [t][h2]; v TRANSPOSED fp16 [b][h][t].
// Also zeroes g_Z.
// ---------------------------------------------------------------------------
__global__ void __launch_bounds__(256, 2) qkv_kernel(
        const float* __restrict__ x,
        const float* __restrict__ Wq,
        const float* __restrict__ Wk,
        const float* __restrict__ Wv) {
    __shared__ float Xs[2][64][36];       // pad ==4 mod 32
    __shared__ float Ws[2][3][32][72];    // pad ==8 mod 32
    const uint32_t XB = (uint32_t)__cvta_generic_to_shared(&Xs[0][0][0]);
    const uint32_t WB = (uint32_t)__cvta_generic_to_shared(&Ws[0][0][0][0]);
    const float* Wmat[3] = {Wq, Wk, Wv};

    const int r0  = blockIdx.x * 64;
    const int tid = threadIdx.x, lane = tid & 31, wid = tid >> 5;
    const int lr = lane >> 2, lc = lane & 3;
    const int wm = (wid >> 2) * 32, wn = (wid & 3) * 16;

    if (tid < 64) g_Z[blockIdx.x * 64 + tid] = 0.f;

    for (int i = tid; i < 512; i += 256) {            // X 64x32
        int r = i >> 3, c4 = i & 7;
        cpa16(XB + (r * 36 + c4 * 4) * 4, x + (size_t)(r0 + r) * CC + c4 * 4);
    }
    for (int i = tid; i < 1536; i += 256) {           // W 3x32x64
        int w = i >> 9, j = i & 511, r = j >> 4, c4 = j & 15;
        cpa16(WB + ((w * 32 + r) * 72 + c4 * 4) * 4, Wmat[w] + (size_t)r * HH + c4 * 4);
    }
    cp_commit();

    float acc[3][2][2][4] = {};
    for (int k0 = 0; k0 < CC; k0 += 32) {
        const int st = (k0 >> 5) & 1;
        if (k0 + 32 < CC) {
            const uint32_t xD = XB + (st ^ 1) * 64 * 36 * 4;
            const uint32_t wD = WB + (st ^ 1) * 3 * 32 * 72 * 4;
            for (int i = tid; i < 512; i += 256) {
                int r = i >> 3, c4 = i & 7;
                cpa16(xD + (r * 36 + c4 * 4) * 4,
                      x + (size_t)(r0 + r) * CC + k0 + 32 + c4 * 4);
            }
            for (int i = tid; i < 1536; i += 256) {
                int w = i >> 9, j = i & 511, r = j >> 4, c4 = j & 15;
                cpa16(wD + ((w * 32 + r) * 72 + c4 * 4) * 4,
                      Wmat[w] + (size_t)(k0 + 32 + r) * HH + c4 * 4);
            }
            cp_commit();
            cp_wait<1>();
        } else {
            cp_wait<0>();
        }
        __syncthreads();

        #pragma unroll
        for (int ks = 0; ks < 4; ks++) {
            const int k = ks * 8;
            uint32_t a[2][4];
            #pragma unroll
            for (int mi = 0; mi < 2; mi++) {
                int rb = wm + mi * 16;
                a[mi][0] = f2tf(Xs[st][rb + lr][k + lc]);
                a[mi][1] = f2tf(Xs[st][rb + lr + 8][k + lc]);
                a[mi][2] = f2tf(Xs[st][rb + lr][k + lc + 4]);
                a[mi][3] = f2tf(Xs[st][rb + lr + 8][k + lc + 4]);
            }
            #pragma unroll
            for (int w = 0; w < 3; w++) {
                uint32_t bf[2][2];
                #pragma unroll
                for (int ni = 0; ni < 2; ni++) {
                    int cb = wn + ni * 8 + lr;
                    bf[ni][0] = f2tf(Ws[st][w][k + lc][cb]);
                    bf[ni][1] = f2tf(Ws[st][w][k + lc + 4][cb]);
                }
                #pragma unroll
                for (int mi = 0; mi < 2; mi++)
                    #pragma unroll
                    for (int ni = 0; ni < 2; ni++)
                        mma8(acc[w][mi][ni], a[mi], bf[ni]);
            }
        }
        __syncthreads();
    }

    // q, k: packed half2
    #pragma unroll
    for (int w = 0; w < 2; w++) {
        uint32_t* dst = &g_qk[(size_t)w * NTOK * HH2];
        #pragma unroll
        for (int mi = 0; mi < 2; mi++)
            #pragma unroll
            for (int ni = 0; ni < 2; ni++) {
                int row = r0 + wm + mi * 16 + lr;
                int c2  = (wn >> 1) + ni * 4 + lc;
                dst[(size_t)row * HH2 + c2]       = f2h2(acc[w][mi][ni][0], acc[w][mi][ni][1]);
                dst[(size_t)(row + 8) * HH2 + c2] = f2h2(acc[w][mi][ni][2], acc[w][mi][ni][3]);
            }
    }
    // v: transposed fp16 scatter
    #pragma unroll
    for (int mi = 0; mi < 2; mi++)
        #pragma unroll
        for (int ni = 0; ni < 2; ni++) {
            int row = r0 + wm + mi * 16 + lr;
            int col = wn + ni * 8 + 2 * lc;
            int b = row >> 11, t = row & 2047;
            size_t base = ((size_t)(b * HH + col)) * TT + t;
            g_vT[base]            = __float2half_rn(acc[2][mi][ni][0]);
            g_vT[base + TT]       = __float2half_rn(acc[2][mi][ni][1]);
            g_vT[base + 8]        = __float2half_rn(acc[2][mi][ni][2]);
            g_vT[base + TT + 8]   = __float2half_rn(acc[2][mi][ni][3]);
        }
}

// ---------------------------------------------------------------------------
// Kernel B: Z[s] = sum_{t>=s} exp(scale*q_t.k_s), fp16 mma k16.
// grid(16 s-tiles, 4 t-chunks, B), 256 thr, K tile persistent, Q dbl-buffered.
// smem: Ks[128][36] + Qs[2][128][36] = 13824 u32 = 55296 B.
// ---------------------------------------------------------------------------
__global__ void __launch_bounds__(256, 2) stats_kernel() {
    extern __shared__ uint32_t sm_[];
    uint32_t (*Ks)[36]      = (uint32_t(*)[36])sm_;
    uint32_t (*Qs)[128][36] = (uint32_t(*)[128][36])(sm_ + 128 * 36);
    const uint32_t sbase = (uint32_t)__cvta_generic_to_shared(sm_);
    const uint32_t KS_B = sbase, QS_B = sbase + 128 * 36 * 4;

    const int si = blockIdx.x, c = blockIdx.y, b = blockIdx.z;
    const int tBeg = max(si, c * 4), tEnd = min(16, c * 4 + 4);
    if (tBeg >= tEnd) return;
    const int s0 = si * 128;
    const uint32_t* q  = &g_qk[(size_t)b * TT * HH2];
    const uint32_t* kp = &g_qk[(size_t)(NTOK + b * TT) * HH2];
    const int tid = threadIdx.x, lane = tid & 31, wid = tid >> 5;
    const int lr = lane >> 2, lc = lane & 3;
    const int wm = (wid >> 2) * 64, wn = (wid & 3) * 32;
    const float scale = rsqrtf((float)CC);

    for (int i = tid; i < 1024; i += 256) {           // K + Q0 tiles 128x32 u32
        int r = i >> 3, c4 = (i & 7) * 4;
        cpa16(KS_B + (r * 36 + c4) * 4, kp + (size_t)(s0 + r) * HH2 + c4);
        cpa16(QS_B + (r * 36 + c4) * 4, q + (size_t)(tBeg * 128 + r) * HH2 + c4);
    }
    cp_commit();

    float colsum[4][2] = {};
    for (int ti = tBeg; ti < tEnd; ti++) {
        const int st = (ti - tBeg) & 1;
        if (ti + 1 < tEnd) {
            const uint32_t dstB = QS_B + (st ^ 1) * 128 * 36 * 4;
            for (int i = tid; i < 1024; i += 256) {
                int r = i >> 3, c4 = (i & 7) * 4;
                cpa16(dstB + (r * 36 + c4) * 4,
                      q + (size_t)((ti + 1) * 128 + r) * HH2 + c4);
            }
            cp_commit();
            cp_wait<1>();
        } else {
            cp_wait<0>();
        }
        __syncthreads();

        const int t0 = ti * 128;
        float acc[4][4][4] = {};
        #pragma unroll
        for (int ks = 0; ks < 4; ks++) {
            const int k = ks * 8;                     // half2 units
            uint32_t a[4][4], bf[4][2];
            #pragma unroll
            for (int mi = 0; mi < 4; mi++) {
                int rb = wm + mi * 16;
                a[mi][0] = Qs[st][rb + lr][k + lc];
                a[mi][1] = Qs[st][rb + lr + 8][k + lc];
                a[mi][2] = Qs[st][rb + lr][k + lc + 4];
                a[mi][3] = Qs[st][rb + lr + 8][k + lc + 4];
            }
            #pragma unroll
            for (int ni = 0; ni < 4; ni++) {
                int sb = wn + ni * 8 + lr;
                bf[ni][0] = Ks[sb][k + lc];
                bf[ni][1] = Ks[sb][k + lc + 4];
            }
            #pragma unroll
            for (int mi = 0; mi < 4; mi++)
                #pragma unroll
                for (int ni = 0; ni < 4; ni++)
                    mma16(acc[mi][ni], a[mi], bf[ni]);
        }

        #pragma unroll
        for (int mi = 0; mi < 4; mi++)
            #pragma unroll
            for (int ni = 0; ni < 4; ni++) {
                int tg = t0 + wm + mi * 16 + lr;
                int sg = s0 + wn + ni * 8 + 2 * lc;
                float e0 = (tg >= sg)         ? __expf(acc[mi][ni][0] * scale) : 0.f;
                float e1 = (tg >= sg + 1)     ? __expf(acc[mi][ni][1] * scale) : 0.f;
                float e2 = (tg + 8 >= sg)     ? __expf(acc[mi][ni][2] * scale) : 0.f;
                float e3 = (tg + 8 >= sg + 1) ? __expf(acc[mi][ni][3] * scale) : 0.f;
                colsum[ni][0] += e0 + e2;
                colsum[ni][1] += e1 + e3;
            }
        __syncthreads();
    }

    #pragma unroll
    for (int ni = 0; ni < 4; ni++)
        #pragma unroll
        for (int jj = 0; jj < 2; jj++) {
            float v = colsum[ni][jj];
            v += __shfl_xor_sync(0xffffffffu, v, 16);
            v += __shfl_xor_sync(0xffffffffu, v, 8);
            v += __shfl_xor_sync(0xffffffffu, v, 4);
            colsum[ni][jj] = v;
        }
    if (lr == 0) {
        #pragma unroll
        for (int ni = 0; ni < 4; ni++) {
            int sg = s0 + wn + ni * 8 + 2 * lc;
            atomicAdd(&g_Z[b * TT + sg],     colsum[ni][0]);
            atomicAdd(&g_Z[b * TT + sg + 1], colsum[ni][1]);
        }
    }
}

// ---------------------------------------------------------------------------
// Kernel C: vT[bh][t] *= 1/Z[b*TT+t], half2 in-place. grid(2048), 256 thr.
// ---------------------------------------------------------------------------
__global__ void vscale_kernel() {
    const int i = blockIdx.x * 256 + threadIdx.x;     // u32 index, TT/2=1024 per row
    const int bh = i >> 10, t0 = (i & 1023) * 2;
    const int b = bh >> 6;
    const float* Zr = &g_Z[b * TT];
    uint32_t* vp = (uint32_t*)g_vT;
    __half2 v = *(__half2*)&vp[i];
    float2 f = __half22float2(v);
    vp[i] = f2h2(f.x * frcp(Zr[t0]), f.y * frcp(Zr[t0 + 1]));
}

// ---------------------------------------------------------------------------
// Kernel D: fused recompute QK^T -> P=exp (fp16) -> PV, all fp16 mma k16.
// Double-buffered K/V. grid(8 s-chunks of 4x64, 16 t-tiles, B), 256 thr.
// smem u32: Qs 0..4608, Ps ..9216, Ks[2] ..13824, Vt[2] ..18432 => 73728 B.
// ---------------------------------------------------------------------------
__global__ void __launch_bounds__(256, 2) pv_kernel(float* __restrict__ out) {
    extern __shared__ uint32_t sm_[];
    uint32_t (*Qs)[36]     = (uint32_t(*)[36])sm_;             // 128 x 32h2
    uint32_t (*Ps)[36]     = (uint32_t(*)[36])(sm_ + 4608);    // 128 x 32h2
    uint32_t (*Ks)[64][36] = (uint32_t(*)[64][36])(sm_ + 9216);
    uint32_t (*Vt)[64][36] = (uint32_t(*)[64][36])(sm_ + 13824);
    const uint32_t sbase = (uint32_t)__cvta_generic_to_shared(sm_);
    const uint32_t QS_B = sbase, KS_B = sbase + 9216 * 4, VT_B = sbase + 13824 * 4;

    const int c = blockIdx.x, ti = blockIdx.y, b = blockIdx.z;
    const int sBeg = c * 4;
    const int sEnd = min(sBeg + 4, 2 * (ti + 1));
    if (sBeg >= sEnd) return;
    const int t0 = ti * 128;

    const uint32_t* q  = &g_qk[(size_t)b * TT * HH2];
    const uint32_t* kp = &g_qk[(size_t)(NTOK + b * TT) * HH2];
    const __half*   vt = &g_vT[(size_t)b * HH * TT];
    const int tid = threadIdx.x, lane = tid & 31, wid = tid >> 5;
    const int lr = lane >> 2, lc = lane & 3;
    const float scale = rsqrtf((float)CC);
    const int wmq = (wid >> 2) * 64, wnq = (wid & 3) * 16;   // QK: 64x16
    const int wm  = (wid >> 1) * 32, wn  = (wid & 1) * 32;   // PV: 32x32

    for (int i = tid; i < 1024; i += 256) {                  // Q 128x32 u32
        int r = i >> 3, c4 = (i & 7) * 4;
        cpa16(QS_B + (r * 36 + c4) * 4, q + (size_t)(t0 + r) * HH2 + c4);
    }
    {
        const int s0 = sBeg * 64;
        for (int i = tid; i < 512; i += 256) {               // K 64x32, Vt 64x32
            int r = i >> 3, c4 = (i & 7) * 4;
            cpa16(KS_B + (r * 36 + c4) * 4, kp + (size_t)(s0 + r) * HH2 + c4);
            cpa16(VT_B + (r * 36 + c4) * 4, vt + (size_t)r * TT + s0 + c4 * 2);
        }
    }
    cp_commit();

    float acc_o[2][4][4] = {};

    for (int s64 = sBeg; s64 < sEnd; s64++) {
        const int st = (s64 - sBeg) & 1;
        cp_wait<0>();
        __syncthreads();

        const int s0 = s64 * 64;
        // --- QK^T: 128x64x64, fp16 ---
        float acc_qk[4][2][4] = {};
        #pragma unroll
        for (int ks = 0; ks < 4; ks++) {
            const int k = ks * 8;
            uint32_t a[4][4], bf[2][2];
            #pragma unroll
            for (int mi = 0; mi < 4; mi++) {
                int rb = wmq + mi * 16;
                a[mi][0] = Qs[rb + lr][k + lc];
                a[mi][1] = Qs[rb + lr + 8][k + lc];
                a[mi][2] = Qs[rb + lr][k + lc + 4];
                a[mi][3] = Qs[rb + lr + 8][k + lc + 4];
            }
            #pragma unroll
            for (int ni = 0; ni < 2; ni++) {
                int sb = wnq + ni * 8 + lr;
                bf[ni][0] = Ks[st][sb][k + lc];
                bf[ni][1] = Ks[st][sb][k + lc + 4];
            }
            #pragma unroll
            for (int mi = 0; mi < 4; mi++)
                #pragma unroll
                for (int ni = 0; ni < 2; ni++)
                    mma16(acc_qk[mi][ni], a[mi], bf[ni]);
        }

        // --- P = exp(S) -> smem as half2 ---
        #pragma unroll
        for (int mi = 0; mi < 4; mi++)
            #pragma unroll
            for (int ni = 0; ni < 2; ni++) {
                int tr = wmq + mi * 16 + lr;
                int sc2 = (wnq >> 1) + ni * 4 + lc;
                int tg = t0 + tr, sg = s0 + wnq + ni * 8 + 2 * lc;
                float e0 = (tg >= sg)     ? __expf(acc_qk[mi][ni][0] * scale) : 0.f;
                float e1 = (tg >= sg + 1) ? __expf(acc_qk[mi][ni][1] * scale) : 0.f;
                Ps[tr][sc2] = f2h2(e0, e1);
                e0 = (tg + 8 >= sg)     ? __expf(acc_qk[mi][ni][2] * scale) : 0.f;
                e1 = (tg + 8 >= sg + 1) ? __expf(acc_qk[mi][ni][3] * scale) : 0.f;
                Ps[tr + 8][sc2] = f2h2(e0, e1);
            }
        __syncthreads();   // Ps visible; K[st] consumed

        if (s64 + 1 < sEnd) {       // prefetch K,V[s+1] -> st^1, overlaps PV
            const int s0n = (s64 + 1) * 64;
            const uint32_t kD = KS_B + (st ^ 1) * 64 * 36 * 4;
            const uint32_t vD = VT_B + (st ^ 1) * 64 * 36 * 4;
            for (int i = tid; i < 512; i += 256) {
                int r = i >> 3, c4 = (i & 7) * 4;
                cpa16(kD + (r * 36 + c4) * 4, kp + (size_t)(s0n + r) * HH2 + c4);
                cpa16(vD + (r * 36 + c4) * 4, vt + (size_t)r * TT + s0n + c4 * 2);
            }
            cp_commit();
        }

        // --- O += P(128x64) @ V(64x64), fp16 (V carries 1/Z) ---
        #pragma unroll
        for (int ks = 0; ks < 4; ks++) {
            const int k = ks * 8;
            uint32_t a[2][4], bf[4][2];
            #pragma unroll
            for (int mi = 0; mi < 2; mi++) {
                int rb = wm + mi * 16;
                a[mi][0] = Ps[rb + lr][k + lc];
                a[mi][1] = Ps[rb + lr + 8][k + lc];
                a[mi][2] = Ps[rb + lr][k + lc + 4];
                a[mi][3] = Ps[rb + lr + 8][k + lc + 4];
            }
            #pragma unroll
            for (int ni = 0; ni < 4; ni++) {
                int cb = wn + ni * 8 + lr;
                bf[ni][0] = Vt[st][cb][k + lc];
                bf[ni][1] = Vt[st][cb][k + lc + 4];
            }
            #pragma unroll
            for (int mi = 0; mi < 2; mi++)
                #pragma unroll
                for (int ni = 0; ni < 4; ni++)
                    mma16(acc_o[mi][ni], a[mi], bf[ni]);
        }
    }

    #pragma unroll
    for (int mi = 0; mi < 2; mi++)
        #pragma unroll
        for (int ni = 0; ni < 4; ni++) {
            int row = b * TT + t0 + wm + mi * 16 + lr;
            int col = wn + ni * 8 + 2 * lc;
            float* o = &out[(size_t)row * HH + col];
            atomicAdd(o,     acc_o[mi][ni][0]);
            atomicAdd(o + 1, acc_o[mi][ni][1]);
            float* o2 = o + 8 * HH;
            atomicAdd(o2,     acc_o[mi][ni][2]);
            atomicAdd(o2 + 1, acc_o[mi][ni][3]);
        }
}

// ---------------------------------------------------------------------------
extern "C" void kernel_launch(void* const* d_in, const int* in_sizes, int n_in,
                              void* d_out, int out_size) {
    const float* x  = (const float*)d_in[0];
    const float* Wq = (const float*)d_in[1];
    const float* Wk = (const float*)d_in[2];
    const float* Wv = (const float*)d_in[3];
    float* out = (float*)d_out;

    const int stats_smem = 3 * 128 * 36 * 4;    // 55296
    const int pv_smem    = 18432 * 4;           // 73728
    cudaFuncSetAttribute(stats_kernel, cudaFuncAttributeMaxDynamicSharedMemorySize, stats_smem);
    cudaFuncSetAttribute(pv_kernel,    cudaFuncAttributeMaxDynamicSharedMemorySize, pv_smem);

    cudaMemsetAsync(d_out, 0, (size_t)out_size * sizeof(float));
    qkv_kernel<<<256, 256>>>(x, Wq, Wk, Wv);
    stats_kernel<<<dim3(16, 4, BB), 256, stats_smem>>>();
    vscale_kernel<<<2048, 256>>>();
    pv_kernel<<<dim3(8, 16, BB), 256, pv_smem>>>(out);
}

// round 15
// speedup vs baseline: 1.3080x; 1.0194x over previous
#include <cuda_runtime.h>
#include <cuda_fp16.h>
#include <math.h>
#include <stdint.h>

#define BB 8
#define TT 2048
#define CC 384
#define HH 64
#define HH2 32                      // half2 per row
#define NTOK (BB * TT)              // 16384

__device__ uint32_t g_qk[2 * NTOK * HH2];   // q | k, packed half2 [tok][h2]
__device__ __half   g_vT[(size_t)NTOK * HH];// v transposed: [(b*HH+h)*TT + t]
__device__ float    g_Z[NTOK];              // per-(b,s) column sum of exp

__device__ __forceinline__ uint32_t f2tf(float f) {
    uint32_t r; asm("cvt.rna.tf32.f32 %0, %1;" : "=r"(r) : "f"(f)); return r;
}
__device__ __forceinline__ uint32_t f2h2(float lo, float hi) {   // pack {lo,hi}
    uint32_t r; asm("cvt.rn.f16x2.f32 %0, %1, %2;" : "=r"(r) : "f"(hi), "f"(lo)); return r;
}
__device__ __forceinline__ float frcp(float f) {
    float r; asm("rcp.approx.f32 %0, %1;" : "=f"(r) : "f"(f)); return r;
}
__device__ __forceinline__ void mma8(float* c, const uint32_t* a, const uint32_t* b) {
    asm volatile(
        "mma.sync.aligned.m16n8k8.row.col.f32.tf32.tf32.f32 "
        "{%0,%1,%2,%3}, {%4,%5,%6,%7}, {%8,%9}, {%0,%1,%2,%3};\n"
        : "+f"(c[0]), "+f"(c[1]), "+f"(c[2]), "+f"(c[3])
        : "r"(a[0]), "r"(a[1]), "r"(a[2]), "r"(a[3]), "r"(b[0]), "r"(b[1]));
}
__device__ __forceinline__ void mma16(float* c, const uint32_t* a, const uint32_t* b) {
    asm volatile(
        "mma.sync.aligned.m16n8k16.row.col.f32.f16.f16.f32 "
        "{%0,%1,%2,%3}, {%4,%5,%6,%7}, {%8,%9}, {%0,%1,%2,%3};\n"
        : "+f"(c[0]), "+f"(c[1]), "+f"(c[2]), "+f"(c[3])
        : "r"(a[0]), "r"(a[1]), "r"(a[2]), "r"(a[3]), "r"(b[0]), "r"(b[1]));
}
__device__ __forceinline__ void ldsm4(uint32_t* r, uint32_t addr) {
    asm volatile("ldmatrix.sync.aligned.m8n8.x4.shared.b16 {%0,%1,%2,%3}, [%4];"
        : "=r"(r[0]), "=r"(r[1]), "=r"(r[2]), "=r"(r[3]) : "r"(addr));
}
__device__ __forceinline__ void cpa16(uint32_t s, const void* g) {
    asm volatile("cp.async.cg.shared.global [%0], [%1], 16;" :: "r"(s), "l"(g));
}
__device__ __forceinline__ void cp_commit() { asm volatile("cp.async.commit_group;"); }
template<int N> __device__ __forceinline__ void cp_wait() {
    asm volatile("cp.async.wait_group %0;" :: "n"(N));
}

// ---------------------------------------------------------------------------
// Kernel A: fused QKV projection (tf32 mma, cvt.rna fragments). grid(256),
// 256 thr. Epilogue: q,k packed half2 [t][h2]; v TRANSPOSED fp16 [b][h][t].
// Zeroes g_Z.
// ---------------------------------------------------------------------------
__global__ void __launch_bounds__(256, 2) qkv_kernel(
        const float* __restrict__ x,
        const float* __restrict__ Wq,
        const float* __restrict__ Wk,
        const float* __restrict__ Wv) {
    __shared__ float Xs[2][64][36];       // pad ==4 mod 32
    __shared__ float Ws[2][3][32][72];    // pad ==8 mod 32
    const uint32_t XB = (uint32_t)__cvta_generic_to_shared(&Xs[0][0][0]);
    const uint32_t WB = (uint32_t)__cvta_generic_to_shared(&Ws[0][0][0][0]);
    const float* Wmat[3] = {Wq, Wk, Wv};

    const int r0  = blockIdx.x * 64;
    const int tid = threadIdx.x, lane = tid & 31, wid = tid >> 5;
    const int lr = lane >> 2, lc = lane & 3;
    const int wm = (wid >> 2) * 32, wn = (wid & 3) * 16;

    if (tid < 64) g_Z[blockIdx.x * 64 + tid] = 0.f;

    for (int i = tid; i < 512; i += 256) {            // X 64x32
        int r = i >> 3, c4 = i & 7;
        cpa16(XB + (r * 36 + c4 * 4) * 4, x + (size_t)(r0 + r) * CC + c4 * 4);
    }
    for (int i = tid; i < 1536; i += 256) {           // W 3x32x64
        int w = i >> 9, j = i & 511, r = j >> 4, c4 = j & 15;
        cpa16(WB + ((w * 32 + r) * 72 + c4 * 4) * 4, Wmat[w] + (size_t)r * HH + c4 * 4);
    }
    cp_commit();

    float acc[3][2][2][4] = {};
    for (int k0 = 0; k0 < CC; k0 += 32) {
        const int st = (k0 >> 5) & 1;
        if (k0 + 32 < CC) {
            const uint32_t xD = XB + (st ^ 1) * 64 * 36 * 4;
            const uint32_t wD = WB + (st ^ 1) * 3 * 32 * 72 * 4;
            for (int i = tid; i < 512; i += 256) {
                int r = i >> 3, c4 = i & 7;
                cpa16(xD + (r * 36 + c4 * 4) * 4,
                      x + (size_t)(r0 + r) * CC + k0 + 32 + c4 * 4);
            }
            for (int i = tid; i < 1536; i += 256) {
                int w = i >> 9, j = i & 511, r = j >> 4, c4 = j & 15;
                cpa16(wD + ((w * 32 + r) * 72 + c4 * 4) * 4,
                      Wmat[w] + (size_t)(k0 + 32 + r) * HH + c4 * 4);
            }
            cp_commit();
            cp_wait<1>();
        } else {
            cp_wait<0>();
        }
        __syncthreads();

        #pragma unroll
        for (int ks = 0; ks < 4; ks++) {
            const int k = ks * 8;
            uint32_t a[2][4];
            #pragma unroll
            for (int mi = 0; mi < 2; mi++) {
                int rb = wm + mi * 16;
                a[mi][0] = f2tf(Xs[st][rb + lr][k + lc]);
                a[mi][1] = f2tf(Xs[st][rb + lr + 8][k + lc]);
                a[mi][2] = f2tf(Xs[st][rb + lr][k + lc + 4]);
                a[mi][3] = f2tf(Xs[st][rb + lr + 8][k + lc + 4]);
            }
            #pragma unroll
            for (int w = 0; w < 3; w++) {
                uint32_t bf[2][2];
                #pragma unroll
                for (int ni = 0; ni < 2; ni++) {
                    int cb = wn + ni * 8 + lr;
                    bf[ni][0] = f2tf(Ws[st][w][k + lc][cb]);
                    bf[ni][1] = f2tf(Ws[st][w][k + lc + 4][cb]);
                }
                #pragma unroll
                for (int mi = 0; mi < 2; mi++)
                    #pragma unroll
                    for (int ni = 0; ni < 2; ni++)
                        mma8(acc[w][mi][ni], a[mi], bf[ni]);
            }
        }
        __syncthreads();
    }

    #pragma unroll
    for (int w = 0; w < 2; w++) {
        uint32_t* dst = &g_qk[(size_t)w * NTOK * HH2];
        #pragma unroll
        for (int mi = 0; mi < 2; mi++)
            #pragma unroll
            for (int ni = 0; ni < 2; ni++) {
                int row = r0 + wm + mi * 16 + lr;
                int c2  = (wn >> 1) + ni * 4 + lc;
                dst[(size_t)row * HH2 + c2]       = f2h2(acc[w][mi][ni][0], acc[w][mi][ni][1]);
                dst[(size_t)(row + 8) * HH2 + c2] = f2h2(acc[w][mi][ni][2], acc[w][mi][ni][3]);
            }
    }
    #pragma unroll
    for (int mi = 0; mi < 2; mi++)
        #pragma unroll
        for (int ni = 0; ni < 2; ni++) {
            int row = r0 + wm + mi * 16 + lr;
            int col = wn + ni * 8 + 2 * lc;
            int b = row >> 11, t = row & 2047;
            size_t base = ((size_t)(b * HH + col)) * TT + t;
            g_vT[base]            = __float2half_rn(acc[2][mi][ni][0]);
            g_vT[base + TT]       = __float2half_rn(acc[2][mi][ni][1]);
            g_vT[base + 8]        = __float2half_rn(acc[2][mi][ni][2]);
            g_vT[base + TT + 8]   = __float2half_rn(acc[2][mi][ni][3]);
        }
}

// ---------------------------------------------------------------------------
// Kernel B: Z[s] = sum_{t>=s} exp(scale*q_t.k_s), fp16 mma k16 + ldmatrix.
// grid(16 s-tiles, 4 t-chunks, B), 256 thr, K persistent, Q dbl-buffered.
// ---------------------------------------------------------------------------
__global__ void __launch_bounds__(256, 2) stats_kernel() {
    extern __shared__ uint32_t sm_[];
    const uint32_t sbase = (uint32_t)__cvta_generic_to_shared(sm_);
    const uint32_t KS_B = sbase, QS_B = sbase + 128 * 36 * 4;

    const int si = blockIdx.x, c = blockIdx.y, b = blockIdx.z;
    const int tBeg = max(si, c * 4), tEnd = min(16, c * 4 + 4);
    if (tBeg >= tEnd) return;
    const int s0 = si * 128;
    const uint32_t* q  = &g_qk[(size_t)b * TT * HH2];
    const uint32_t* kp = &g_qk[(size_t)(NTOK + b * TT) * HH2];
    const int tid = threadIdx.x, lane = tid & 31, wid = tid >> 5;
    const int lr = lane >> 2, lc = lane & 3;
    const int mg = lane >> 3, rr = lane & 7;
    const int aoff = (((mg & 1) * 8 + rr) * 36 + (mg >> 1) * 4) * 4;   // bytes
    const int boff = (((mg >> 1) * 8 + rr) * 36 + (mg & 1) * 4) * 4;
    const int wm = (wid >> 2) * 64, wn = (wid & 3) * 32;
    const float scale = rsqrtf((float)CC);

    for (int i = tid; i < 1024; i += 256) {
        int r = i >> 3, c4 = (i & 7) * 4;
        cpa16(KS_B + (r * 36 + c4) * 4, kp + (size_t)(s0 + r) * HH2 + c4);
        cpa16(QS_B + (r * 36 + c4) * 4, q + (size_t)(tBeg * 128 + r) * HH2 + c4);
    }
    cp_commit();

    float colsum[4][2] = {};
    for (int ti = tBeg; ti < tEnd; ti++) {
        const int st = (ti - tBeg) & 1;
        if (ti + 1 < tEnd) {
            const uint32_t dstB = QS_B + (st ^ 1) * 128 * 36 * 4;
            for (int i = tid; i < 1024; i += 256) {
                int r = i >> 3, c4 = (i & 7) * 4;
                cpa16(dstB + (r * 36 + c4) * 4,
                      q + (size_t)((ti + 1) * 128 + r) * HH2 + c4);
            }
            cp_commit();
            cp_wait<1>();
        } else {
            cp_wait<0>();
        }
        __syncthreads();

        const uint32_t QB = QS_B + st * 128 * 36 * 4;
        const int t0 = ti * 128;
        float acc[4][4][4] = {};
        #pragma unroll
        for (int ks = 0; ks < 4; ks++) {
            const int k = ks * 8;
            uint32_t a[4][4], bf[4][2], btmp[4];
            #pragma unroll
            for (int mi = 0; mi < 4; mi++)
                ldsm4(a[mi], QB + ((wm + mi * 16) * 36 + k) * 4 + aoff);
            ldsm4(btmp, KS_B + (wn * 36 + k) * 4 + boff);
            bf[0][0] = btmp[0]; bf[0][1] = btmp[1]; bf[1][0] = btmp[2]; bf[1][1] = btmp[3];
            ldsm4(btmp, KS_B + ((wn + 16) * 36 + k) * 4 + boff);
            bf[2][0] = btmp[0]; bf[2][1] = btmp[1]; bf[3][0] = btmp[2]; bf[3][1] = btmp[3];
            #pragma unroll
            for (int mi = 0; mi < 4; mi++)
                #pragma unroll
                for (int ni = 0; ni < 4; ni++)
                    mma16(acc[mi][ni], a[mi], bf[ni]);
        }

        #pragma unroll
        for (int mi = 0; mi < 4; mi++)
            #pragma unroll
            for (int ni = 0; ni < 4; ni++) {
                int tg = t0 + wm + mi * 16 + lr;
                int sg = s0 + wn + ni * 8 + 2 * lc;
                float e0 = (tg >= sg)         ? __expf(acc[mi][ni][0] * scale) : 0.f;
                float e1 = (tg >= sg + 1)     ? __expf(acc[mi][ni][1] * scale) : 0.f;
                float e2 = (tg + 8 >= sg)     ? __expf(acc[mi][ni][2] * scale) : 0.f;
                float e3 = (tg + 8 >= sg + 1) ? __expf(acc[mi][ni][3] * scale) : 0.f;
                colsum[ni][0] += e0 + e2;
                colsum[ni][1] += e1 + e3;
            }
        __syncthreads();
    }

    #pragma unroll
    for (int ni = 0; ni < 4; ni++)
        #pragma unroll
        for (int jj = 0; jj < 2; jj++) {
            float v = colsum[ni][jj];
            v += __shfl_xor_sync(0xffffffffu, v, 16);
            v += __shfl_xor_sync(0xffffffffu, v, 8);
            v += __shfl_xor_sync(0xffffffffu, v, 4);
            colsum[ni][jj] = v;
        }
    if (lr == 0) {
        #pragma unroll
        for (int ni = 0; ni < 4; ni++) {
            int sg = s0 + wn + ni * 8 + 2 * lc;
            atomicAdd(&g_Z[b * TT + sg],     colsum[ni][0]);
            atomicAdd(&g_Z[b * TT + sg + 1], colsum[ni][1]);
        }
    }
}

// ---------------------------------------------------------------------------
// Kernel C: vT[bh][t] *= 1/Z[b*TT+t], half2 in-place. grid(2048), 256 thr.
// ---------------------------------------------------------------------------
__global__ void vscale_kernel() {
    const int i = blockIdx.x * 256 + threadIdx.x;
    const int bh = i >> 10, t0 = (i & 1023) * 2;
    const int b = bh >> 6;
    const float* Zr = &g_Z[b * TT];
    uint32_t* vp = (uint32_t*)g_vT;
    __half2 v = *(__half2*)&vp[i];
    float2 f = __half22float2(v);
    vp[i] = f2h2(f.x * frcp(Zr[t0]), f.y * frcp(Zr[t0 + 1]));
}

// ---------------------------------------------------------------------------
// Kernel D: fused QK^T -> P=exp -> PV, fp16 mma + ldmatrix, dbl-buffered K/V.
// grid(8 s-chunks of 4x64, 16 t-tiles, B), 256 thr. smem 73728 B.
// ---------------------------------------------------------------------------
__global__ void __launch_bounds__(256, 2) pv_kernel(float* __restrict__ out) {
    extern __shared__ uint32_t sm_[];
    uint32_t (*Ps)[36] = (uint32_t(*)[36])(sm_ + 4608);
    const uint32_t sbase = (uint32_t)__cvta_generic_to_shared(sm_);
    const uint32_t QS_B = sbase, PS_B = sbase + 4608 * 4,
                   KS_B = sbase + 9216 * 4, VT_B = sbase + 13824 * 4;

    const int c = blockIdx.x, ti = blockIdx.y, b = blockIdx.z;
    const int sBeg = c * 4;
    const int sEnd = min(sBeg + 4, 2 * (ti + 1));
    if (sBeg >= sEnd) return;
    const int t0 = ti * 128;

    const uint32_t* q  = &g_qk[(size_t)b * TT * HH2];
    const uint32_t* kp = &g_qk[(size_t)(NTOK + b * TT) * HH2];
    const __half*   vt = &g_vT[(size_t)b * HH * TT];
    const int tid = threadIdx.x, lane = tid & 31, wid = tid >> 5;
    const int lr = lane >> 2, lc = lane & 3;
    const int mg = lane >> 3, rr = lane & 7;
    const int aoff = (((mg & 1) * 8 + rr) * 36 + (mg >> 1) * 4) * 4;   // bytes
    const int boff = (((mg >> 1) * 8 + rr) * 36 + (mg & 1) * 4) * 4;
    const float scale = rsqrtf((float)CC);
    const int wmq = (wid >> 2) * 64, wnq = (wid & 3) * 16;   // QK: 64x16
    const int wm  = (wid >> 1) * 32, wn  = (wid & 1) * 32;   // PV: 32x32

    for (int i = tid; i < 1024; i += 256) {
        int r = i >> 3, c4 = (i & 7) * 4;
        cpa16(QS_B + (r * 36 + c4) * 4, q + (size_t)(t0 + r) * HH2 + c4);
    }
    {
        const int s0 = sBeg * 64;
        for (int i = tid; i < 512; i += 256) {
            int r = i >> 3, c4 = (i & 7) * 4;
            cpa16(KS_B + (r * 36 + c4) * 4, kp + (size_t)(s0 + r) * HH2 + c4);
            cpa16(VT_B + (r * 36 + c4) * 4, vt + (size_t)r * TT + s0 + c4 * 2);
        }
    }
    cp_commit();

    float acc_o[2][4][4] = {};

    for (int s64 = sBeg; s64 < sEnd; s64++) {
        const int st = (s64 - sBeg) & 1;
        const uint32_t stoff = st * 64 * 36 * 4;
        cp_wait<0>();
        __syncthreads();

        const int s0 = s64 * 64;
        // --- QK^T: 128x64x64 ---
        float acc_qk[4][2][4] = {};
        #pragma unroll
        for (int ks = 0; ks < 4; ks++) {
            const int k = ks * 8;
            uint32_t a[4][4], bf[4];
            #pragma unroll
            for (int mi = 0; mi < 4; mi++)
                ldsm4(a[mi], QS_B + ((wmq + mi * 16) * 36 + k) * 4 + aoff);
            ldsm4(bf, KS_B + stoff + (wnq * 36 + k) * 4 + boff);
            #pragma unroll
            for (int mi = 0; mi < 4; mi++) {
                mma16(acc_qk[mi][0], a[mi], bf);
                mma16(acc_qk[mi][1], a[mi], bf + 2);
            }
        }

        // --- P = exp(S) -> smem half2 ---
        #pragma unroll
        for (int mi = 0; mi < 4; mi++)
            #pragma unroll
            for (int ni = 0; ni < 2; ni++) {
                int tr = wmq + mi * 16 + lr;
                int sc2 = (wnq >> 1) + ni * 4 + lc;
                int tg = t0 + tr, sg = s0 + wnq + ni * 8 + 2 * lc;
                float e0 = (tg >= sg)     ? __expf(acc_qk[mi][ni][0] * scale) : 0.f;
                float e1 = (tg >= sg + 1) ? __expf(acc_qk[mi][ni][1] * scale) : 0.f;
                Ps[tr][sc2] = f2h2(e0, e1);
                e0 = (tg + 8 >= sg)     ? __expf(acc_qk[mi][ni][2] * scale) : 0.f;
                e1 = (tg + 8 >= sg + 1) ? __expf(acc_qk[mi][ni][3] * scale) : 0.f;
                Ps[tr + 8][sc2] = f2h2(e0, e1);
            }
        __syncthreads();

        if (s64 + 1 < sEnd) {       // prefetch K,V[s+1] over PV phase
            const int s0n = (s64 + 1) * 64;
            const uint32_t kD = KS_B + (stoff ^ (64 * 36 * 4));
            const uint32_t vD = VT_B + (stoff ^ (64 * 36 * 4));
            for (int i = tid; i < 512; i += 256) {
                int r = i >> 3, c4 = (i & 7) * 4;
                cpa16(kD + (r * 36 + c4) * 4, kp + (size_t)(s0n + r) * HH2 + c4);
                cpa16(vD + (r * 36 + c4) * 4, vt + (size_t)r * TT + s0n + c4 * 2);
            }
            cp_commit();
        }

        // --- O += P(128x64) @ V(64x64) ---
        #pragma unroll
        for (int ks = 0; ks < 4; ks++) {
            const int k = ks * 8;
            uint32_t a[2][4], b0[4], b1[4];
            #pragma unroll
            for (int mi = 0; mi < 2; mi++)
                ldsm4(a[mi], PS_B + ((wm + mi * 16) * 36 + k) * 4 + aoff);
            ldsm4(b0, VT_B + stoff + (wn * 36 + k) * 4 + boff);
            ldsm4(b1, VT_B + stoff + ((wn + 16) * 36 + k) * 4 + boff);
            #pragma unroll
            for (int mi = 0; mi < 2; mi++) {
                mma16(acc_o[mi][0], a[mi], b0);
                mma16(acc_o[mi][1], a[mi], b0 + 2);
                mma16(acc_o[mi][2], a[mi], b1);
                mma16(acc_o[mi][3], a[mi], b1 + 2);
            }
        }
    }

    #pragma unroll
    for (int mi = 0; mi < 2; mi++)
        #pragma unroll
        for (int ni = 0; ni < 4; ni++) {
            int row = b * TT + t0 + wm + mi * 16 + lr;
            int col = wn + ni * 8 + 2 * lc;
            float* o = &out[(size_t)row * HH + col];
            atomicAdd(o,     acc_o[mi][ni][0]);
            atomicAdd(o + 1, acc_o[mi][ni][1]);
            float* o2 = o + 8 * HH;
            atomicAdd(o2,     acc_o[mi][ni][2]);
            atomicAdd(o2 + 1, acc_o[mi][ni][3]);
        }
}

// ---------------------------------------------------------------------------
extern "C" void kernel_launch(void* const* d_in, const int* in_sizes, int n_in,
                              void* d_out, int out_size) {
    const float* x  = (const float*)d_in[0];
    const float* Wq = (const float*)d_in[1];
    const float* Wk = (const float*)d_in[2];
    const float* Wv = (const float*)d_in[3];
    float* out = (float*)d_out;

    const int stats_smem = 3 * 128 * 36 * 4;    // 55296
    const int pv_smem    = 18432 * 4;           // 73728
    cudaFuncSetAttribute(stats_kernel, cudaFuncAttributeMaxDynamicSharedMemorySize, stats_smem);
    cudaFuncSetAttribute(pv_kernel,    cudaFuncAttributeMaxDynamicSharedMemorySize, pv_smem);

    cudaMemsetAsync(d_out, 0, (size_t)out_size * sizeof(float));
    qkv_kernel<<<256, 256>>>(x, Wq, Wk, Wv);
    stats_kernel<<<dim3(16, 4, BB), 256, stats_smem>>>();
    vscale_kernel<<<2048, 256>>>();
    pv_kernel<<<dim3(8, 16, BB), 256, pv_smem>>>(out);
}

// round 16
// speedup vs baseline: 1.4355x; 1.0975x over previous
#include <cuda_runtime.h>
#include <cuda_fp16.h>
#include <math.h>
#include <stdint.h>

#define BB 8
#define TT 2048
#define CC 384
#define HH 64
#define HH2 32                      // half2 per row
#define NTOK (BB * TT)              // 16384

__device__ uint32_t g_qk[2 * NTOK * HH2];   // q | k, packed half2 [tok][h2]
__device__ __half   g_vT[(size_t)NTOK * HH];// v transposed: [(b*HH+h)*TT + t]
__device__ __half   g_wh[3 * CC * HH];      // Wq|Wk|Wv fp16, [w][k][n]
__device__ float    g_Z[NTOK];              // per-(b,s) column sum of exp

__device__ __forceinline__ uint32_t f2h2(float lo, float hi) {   // pack {lo,hi}
    uint32_t r; asm("cvt.rn.f16x2.f32 %0, %1, %2;" : "=r"(r) : "f"(hi), "f"(lo)); return r;
}
__device__ __forceinline__ float frcp(float f) {
    float r; asm("rcp.approx.f32 %0, %1;" : "=f"(r) : "f"(f)); return r;
}
__device__ __forceinline__ void mma16(float* c, const uint32_t* a, const uint32_t* b) {
    asm volatile(
        "mma.sync.aligned.m16n8k16.row.col.f32.f16.f16.f32 "
        "{%0,%1,%2,%3}, {%4,%5,%6,%7}, {%8,%9}, {%0,%1,%2,%3};\n"
        : "+f"(c[0]), "+f"(c[1]), "+f"(c[2]), "+f"(c[3])
        : "r"(a[0]), "r"(a[1]), "r"(a[2]), "r"(a[3]), "r"(b[0]), "r"(b[1]));
}
__device__ __forceinline__ void ldsm4(uint32_t* r, uint32_t addr) {
    asm volatile("ldmatrix.sync.aligned.m8n8.x4.shared.b16 {%0,%1,%2,%3}, [%4];"
        : "=r"(r[0]), "=r"(r[1]), "=r"(r[2]), "=r"(r[3]) : "r"(addr));
}
__device__ __forceinline__ void ldsm4t(uint32_t* r, uint32_t addr) {
    asm volatile("ldmatrix.sync.aligned.m8n8.x4.trans.shared.b16 {%0,%1,%2,%3}, [%4];"
        : "=r"(r[0]), "=r"(r[1]), "=r"(r[2]), "=r"(r[3]) : "r"(addr));
}
__device__ __forceinline__ void cpa16(uint32_t s, const void* g) {
    asm volatile("cp.async.cg.shared.global [%0], [%1], 16;" :: "r"(s), "l"(g));
}
__device__ __forceinline__ void cp_commit() { asm volatile("cp.async.commit_group;"); }
template<int N> __device__ __forceinline__ void cp_wait() {
    asm volatile("cp.async.wait_group %0;" :: "n"(N));
}

// ---------------------------------------------------------------------------
// Kernel W: convert Wq|Wk|Wv fp32 -> fp16 into g_wh. grid(72), 256 thr.
// ---------------------------------------------------------------------------
__global__ void wconv_kernel(const float* __restrict__ Wq,
                             const float* __restrict__ Wk,
                             const float* __restrict__ Wv) {
    const int i = blockIdx.x * 256 + threadIdx.x;   // float4 index, 18432 total
    const int e = i * 4;
    const int w = e / (CC * HH);
    const int off = e - w * (CC * HH);
    const float* W = (w == 0) ? Wq : ((w == 1) ? Wk : Wv);
    float4 v = *(const float4*)&W[off];
    *(uint2*)((__half*)g_wh + e) = make_uint2(f2h2(v.x, v.y), f2h2(v.z, v.w));
}

// ---------------------------------------------------------------------------
// Kernel A: fused QKV projection, fp16 mma + ldmatrix(+trans for W).
// grid(128), 256 thr. X converted in-register on load. Zeroes g_Z.
// smem u32: Xh[2][128][36]=9216, Wh[2][3][64][36]=13824 -> 92160 B dynamic.
// ---------------------------------------------------------------------------
__global__ void __launch_bounds__(256, 1) qkv_kernel(const float* __restrict__ x) {
    extern __shared__ uint32_t sm_[];
    uint32_t (*Xh)[128][36] = (uint32_t(*)[128][36])sm_;
    const uint32_t sbase = (uint32_t)__cvta_generic_to_shared(sm_);
    const uint32_t XH_B = sbase, WH_B = sbase + 9216 * 4;

    const int r0  = blockIdx.x * 128;
    const int tid = threadIdx.x, lane = tid & 31, wid = tid >> 5;
    const int lr = lane >> 2, lc = lane & 3;
    const int mg = lane >> 3, rr = lane & 7;
    const int loff = (((mg & 1) * 8 + rr) * 36 + (mg >> 1) * 4) * 4;  // A & B-trans
    const int wm = (wid >> 1) * 32, wn = (wid & 1) * 32;

    if (tid < 128) g_Z[blockIdx.x * 128 + tid] = 0.f;

    // X tile load+convert (LDG fp32 -> fp16 STS), 128x64 per k-tile
    auto loadX = [&](int k0, int st) {
        #pragma unroll
        for (int j = 0; j < 8; j++) {
            int idx = tid + j * 256;
            int r = idx >> 4, c4 = idx & 15;
            float4 v = *(const float4*)&x[(size_t)(r0 + r) * CC + k0 + c4 * 4];
            Xh[st][r][c4 * 2]     = f2h2(v.x, v.y);
            Xh[st][r][c4 * 2 + 1] = f2h2(v.z, v.w);
        }
    };
    // W tiles (fp16 global) via cp.async: 3 x 64rows x 64halves
    auto loadW = [&](int k0, int st) {
        const uint32_t dst = WH_B + st * 6912 * 4;
        for (int i = tid; i < 1536; i += 256) {
            int row = i >> 3, seg = i & 7;
            int w = row >> 6, kr = row & 63;
            cpa16(dst + (row * 36 + seg * 4) * 4,
                  (const __half*)g_wh + ((size_t)(w * CC + k0 + kr) * HH) + seg * 8);
        }
    };

    loadX(0, 0);
    loadW(0, 0);
    cp_commit();

    float acc[3][2][4][4] = {};
    for (int kt = 0; kt < 6; kt++) {
        const int st = kt & 1;
        if (kt + 1 < 6) {
            loadX((kt + 1) * 64, st ^ 1);
            loadW((kt + 1) * 64, st ^ 1);
            cp_commit();
            cp_wait<1>();
        } else {
            cp_wait<0>();
        }
        __syncthreads();

        const uint32_t XB = XH_B + st * 4608 * 4;
        const uint32_t WB = WH_B + st * 6912 * 4;
        #pragma unroll
        for (int ks = 0; ks < 4; ks++) {
            uint32_t a[2][4];
            #pragma unroll
            for (int mi = 0; mi < 2; mi++)
                ldsm4(a[mi], XB + ((wm + mi * 16) * 36 + ks * 8) * 4 + loff);
            #pragma unroll
            for (int w = 0; w < 3; w++) {
                uint32_t b0[4], b1[4];
                ldsm4t(b0, WB + ((w * 64 + ks * 16) * 36 + (wn >> 1)) * 4 + loff);
                ldsm4t(b1, WB + ((w * 64 + ks * 16) * 36 + (wn >> 1) + 8) * 4 + loff);
                #pragma unroll
                for (int mi = 0; mi < 2; mi++) {
                    mma16(acc[w][mi][0], a[mi], b0);
                    mma16(acc[w][mi][1], a[mi], b0 + 2);
                    mma16(acc[w][mi][2], a[mi], b1);
                    mma16(acc[w][mi][3], a[mi], b1 + 2);
                }
            }
        }
        __syncthreads();
    }

    // q, k: packed half2 [t][h2]
    #pragma unroll
    for (int w = 0; w < 2; w++) {
        uint32_t* dst = &g_qk[(size_t)w * NTOK * HH2];
        #pragma unroll
        for (int mi = 0; mi < 2; mi++)
            #pragma unroll
            for (int ni = 0; ni < 4; ni++) {
                int row = r0 + wm + mi * 16 + lr;
                int c2  = (wn >> 1) + ni * 4 + lc;
                dst[(size_t)row * HH2 + c2]       = f2h2(acc[w][mi][ni][0], acc[w][mi][ni][1]);
                dst[(size_t)(row + 8) * HH2 + c2] = f2h2(acc[w][mi][ni][2], acc[w][mi][ni][3]);
            }
    }
    // v: transposed fp16 scatter [b][h][t]
    #pragma unroll
    for (int mi = 0; mi < 2; mi++)
        #pragma unroll
        for (int ni = 0; ni < 4; ni++) {
            int row = r0 + wm + mi * 16 + lr;
            int col = wn + ni * 8 + 2 * lc;
            int b = row >> 11, t = row & 2047;
            size_t base = ((size_t)(b * HH + col)) * TT + t;
            g_vT[base]          = __float2half_rn(acc[2][mi][ni][0]);
            g_vT[base + TT]     = __float2half_rn(acc[2][mi][ni][1]);
            g_vT[base + 8]      = __float2half_rn(acc[2][mi][ni][2]);
            g_vT[base + TT + 8] = __float2half_rn(acc[2][mi][ni][3]);
        }
}

// ---------------------------------------------------------------------------
// Kernel B: Z[s] = sum_{t>=s} exp(scale*q_t.k_s), fp16 mma k16 + ldmatrix.
// grid(16 s-tiles, 4 t-chunks, B), 256 thr, K persistent, Q dbl-buffered.
// ---------------------------------------------------------------------------
__global__ void __launch_bounds__(256, 2) stats_kernel() {
    extern __shared__ uint32_t sm_[];
    const uint32_t sbase = (uint32_t)__cvta_generic_to_shared(sm_);
    const uint32_t KS_B = sbase, QS_B = sbase + 128 * 36 * 4;

    const int si = blockIdx.x, c = blockIdx.y, b = blockIdx.z;
    const int tBeg = max(si, c * 4), tEnd = min(16, c * 4 + 4);
    if (tBeg >= tEnd) return;
    const int s0 = si * 128;
    const uint32_t* q  = &g_qk[(size_t)b * TT * HH2];
    const uint32_t* kp = &g_qk[(size_t)(NTOK + b * TT) * HH2];
    const int tid = threadIdx.x, lane = tid & 31, wid = tid >> 5;
    const int lr = lane >> 2, lc = lane & 3;
    const int mg = lane >> 3, rr = lane & 7;
    const int aoff = (((mg & 1) * 8 + rr) * 36 + (mg >> 1) * 4) * 4;   // bytes
    const int boff = (((mg >> 1) * 8 + rr) * 36 + (mg & 1) * 4) * 4;
    const int wm = (wid >> 2) * 64, wn = (wid & 3) * 32;
    const float scale = rsqrtf((float)CC);

    for (int i = tid; i < 1024; i += 256) {
        int r = i >> 3, c4 = (i & 7) * 4;
        cpa16(KS_B + (r * 36 + c4) * 4, kp + (size_t)(s0 + r) * HH2 + c4);
        cpa16(QS_B + (r * 36 + c4) * 4, q + (size_t)(tBeg * 128 + r) * HH2 + c4);
    }
    cp_commit();

    float colsum[4][2] = {};
    for (int ti = tBeg; ti < tEnd; ti++) {
        const int st = (ti - tBeg) & 1;
        if (ti + 1 < tEnd) {
            const uint32_t dstB = QS_B + (st ^ 1) * 128 * 36 * 4;
            for (int i = tid; i < 1024; i += 256) {
                int r = i >> 3, c4 = (i & 7) * 4;
                cpa16(dstB + (r * 36 + c4) * 4,
                      q + (size_t)((ti + 1) * 128 + r) * HH2 + c4);
            }
            cp_commit();
            cp_wait<1>();
        } else {
            cp_wait<0>();
        }
        __syncthreads();

        const uint32_t QB = QS_B + st * 128 * 36 * 4;
        const int t0 = ti * 128;
        float acc[4][4][4] = {};
        #pragma unroll
        for (int ks = 0; ks < 4; ks++) {
            const int k = ks * 8;
            uint32_t a[4][4], bf[4][2], btmp[4];
            #pragma unroll
            for (int mi = 0; mi < 4; mi++)
                ldsm4(a[mi], QB + ((wm + mi * 16) * 36 + k) * 4 + aoff);
            ldsm4(btmp, KS_B + (wn * 36 + k) * 4 + boff);
            bf[0][0] = btmp[0]; bf[0][1] = btmp[1]; bf[1][0] = btmp[2]; bf[1][1] = btmp[3];
            ldsm4(btmp, KS_B + ((wn + 16) * 36 + k) * 4 + boff);
            bf[2][0] = btmp[0]; bf[2][1] = btmp[1]; bf[3][0] = btmp[2]; bf[3][1] = btmp[3];
            #pragma unroll
            for (int mi = 0; mi < 4; mi++)
                #pragma unroll
                for (int ni = 0; ni < 4; ni++)
                    mma16(acc[mi][ni], a[mi], bf[ni]);
        }

        #pragma unroll
        for (int mi = 0; mi < 4; mi++)
            #pragma unroll
            for (int ni = 0; ni < 4; ni++) {
                int tg = t0 + wm + mi * 16 + lr;
                int sg = s0 + wn + ni * 8 + 2 * lc;
                float e0 = (tg >= sg)         ? __expf(acc[mi][ni][0] * scale) : 0.f;
                float e1 = (tg >= sg + 1)     ? __expf(acc[mi][ni][1] * scale) : 0.f;
                float e2 = (tg + 8 >= sg)     ? __expf(acc[mi][ni][2] * scale) : 0.f;
                float e3 = (tg + 8 >= sg + 1) ? __expf(acc[mi][ni][3] * scale) : 0.f;
                colsum[ni][0] += e0 + e2;
                colsum[ni][1] += e1 + e3;
            }
        __syncthreads();
    }

    #pragma unroll
    for (int ni = 0; ni < 4; ni++)
        #pragma unroll
        for (int jj = 0; jj < 2; jj++) {
            float v = colsum[ni][jj];
            v += __shfl_xor_sync(0xffffffffu, v, 16);
            v += __shfl_xor_sync(0xffffffffu, v, 8);
            v += __shfl_xor_sync(0xffffffffu, v, 4);
            colsum[ni][jj] = v;
        }
    if (lr == 0) {
        #pragma unroll
        for (int ni = 0; ni < 4; ni++) {
            int sg = s0 + wn + ni * 8 + 2 * lc;
            atomicAdd(&g_Z[b * TT + sg],     colsum[ni][0]);
            atomicAdd(&g_Z[b * TT + sg + 1], colsum[ni][1]);
        }
    }
}

// ---------------------------------------------------------------------------
// Kernel C: vT[bh][t] *= 1/Z[b*TT+t], half2 in-place. grid(2048), 256 thr.
// ---------------------------------------------------------------------------
__global__ void vscale_kernel() {
    const int i = blockIdx.x * 256 + threadIdx.x;
    const int bh = i >> 10, t0 = (i & 1023) * 2;
    const int b = bh >> 6;
    const float* Zr = &g_Z[b * TT];
    uint32_t* vp = (uint32_t*)g_vT;
    __half2 v = *(__half2*)&vp[i];
    float2 f = __half22float2(v);
    vp[i] = f2h2(f.x * frcp(Zr[t0]), f.y * frcp(Zr[t0 + 1]));
}

// ---------------------------------------------------------------------------
// Kernel D: fused QK^T -> P=exp -> PV, fp16 mma + ldmatrix, dbl-buffered K/V.
// QK warps 4m x 2n with Q-fragments hoisted into registers (loaded once).
// grid(8 s-chunks of 4x64, 16 t-tiles, B), 256 thr. smem 73728 B.
// ---------------------------------------------------------------------------
__global__ void __launch_bounds__(256, 2) pv_kernel(float* __restrict__ out) {
    extern __shared__ uint32_t sm_[];
    uint32_t (*Ps)[36] = (uint32_t(*)[36])(sm_ + 4608);
    const uint32_t sbase = (uint32_t)__cvta_generic_to_shared(sm_);
    const uint32_t QS_B = sbase, PS_B = sbase + 4608 * 4,
                   KS_B = sbase + 9216 * 4, VT_B = sbase + 13824 * 4;

    const int c = blockIdx.x, ti = blockIdx.y, b = blockIdx.z;
    const int sBeg = c * 4;
    const int sEnd = min(sBeg + 4, 2 * (ti + 1));
    if (sBeg >= sEnd) return;
    const int t0 = ti * 128;

    const uint32_t* q  = &g_qk[(size_t)b * TT * HH2];
    const uint32_t* kp = &g_qk[(size_t)(NTOK + b * TT) * HH2];
    const __half*   vt = &g_vT[(size_t)b * HH * TT];
    const int tid = threadIdx.x, lane = tid & 31, wid = tid >> 5;
    const int lr = lane >> 2, lc = lane & 3;
    const int mg = lane >> 3, rr = lane & 7;
    const int aoff = (((mg & 1) * 8 + rr) * 36 + (mg >> 1) * 4) * 4;   // bytes
    const int boff = (((mg >> 1) * 8 + rr) * 36 + (mg & 1) * 4) * 4;
    const float scale = rsqrtf((float)CC);
    const int wm = (wid >> 1) * 32, wn = (wid & 1) * 32;  // both QK and PV

    for (int i = tid; i < 1024; i += 256) {
        int r = i >> 3, c4 = (i & 7) * 4;
        cpa16(QS_B + (r * 36 + c4) * 4, q + (size_t)(t0 + r) * HH2 + c4);
    }
    {
        const int s0 = sBeg * 64;
        for (int i = tid; i < 512; i += 256) {
            int r = i >> 3, c4 = (i & 7) * 4;
            cpa16(KS_B + (r * 36 + c4) * 4, kp + (size_t)(s0 + r) * HH2 + c4);
            cpa16(VT_B + (r * 36 + c4) * 4, vt + (size_t)r * TT + s0 + c4 * 2);
        }
    }
    cp_commit();

    uint32_t qf[2][4][4];        // hoisted Q fragments: [mi][ks][4]
    float acc_o[2][4][4] = {};

    for (int s64 = sBeg; s64 < sEnd; s64++) {
        const int st = (s64 - sBeg) & 1;
        const uint32_t stoff = st * 64 * 36 * 4;
        cp_wait<0>();
        __syncthreads();

        if (s64 == sBeg) {       // one-time Q fragment load
            #pragma unroll
            for (int mi = 0; mi < 2; mi++)
                #pragma unroll
                for (int ks = 0; ks < 4; ks++)
                    ldsm4(qf[mi][ks], QS_B + ((wm + mi * 16) * 36 + ks * 8) * 4 + aoff);
        }

        const int s0 = s64 * 64;
        // --- QK^T: 128x64x64, warp tile 32x32 ---
        float acc_qk[2][4][4] = {};
        #pragma unroll
        for (int ks = 0; ks < 4; ks++) {
            const int k = ks * 8;
            uint32_t b0[4], b1[4];
            ldsm4(b0, KS_B + stoff + (wn * 36 + k) * 4 + boff);
            ldsm4(b1, KS_B + stoff + ((wn + 16) * 36 + k) * 4 + boff);
            #pragma unroll
            for (int mi = 0; mi < 2; mi++) {
                mma16(acc_qk[mi][0], qf[mi][ks], b0);
                mma16(acc_qk[mi][1], qf[mi][ks], b0 + 2);
                mma16(acc_qk[mi][2], qf[mi][ks], b1);
                mma16(acc_qk[mi][3], qf[mi][ks], b1 + 2);
            }
        }

        // --- P = exp(S) -> smem half2 ---
        #pragma unroll
        for (int mi = 0; mi < 2; mi++)
            #pragma unroll
            for (int ni = 0; ni < 4; ni++) {
                int tr = wm + mi * 16 + lr;
                int sc2 = (wn >> 1) + ni * 4 + lc;
                int tg = t0 + tr, sg = s0 + wn + ni * 8 + 2 * lc;
                float e0 = (tg >= sg)     ? __expf(acc_qk[mi][ni][0] * scale) : 0.f;
                float e1 = (tg >= sg + 1) ? __expf(acc_qk[mi][ni][1] * scale) : 0.f;
                Ps[tr][sc2] = f2h2(e0, e1);
                e0 = (tg + 8 >= sg)     ? __expf(acc_qk[mi][ni][2] * scale) : 0.f;
                e1 = (tg + 8 >= sg + 1) ? __expf(acc_qk[mi][ni][3] * scale) : 0.f;
                Ps[tr + 8][sc2] = f2h2(e0, e1);
            }
        __syncthreads();

        if (s64 + 1 < sEnd) {       // prefetch K,V[s+1] over PV phase
            const int s0n = (s64 + 1) * 64;
            const uint32_t kD = KS_B + (stoff ^ (64 * 36 * 4));
            const uint32_t vD = VT_B + (stoff ^ (64 * 36 * 4));
            for (int i = tid; i < 512; i += 256) {
                int r = i >> 3, c4 = (i & 7) * 4;
                cpa16(kD + (r * 36 + c4) * 4, kp + (size_t)(s0n + r) * HH2 + c4);
                cpa16(vD + (r * 36 + c4) * 4, vt + (size_t)r * TT + s0n + c4 * 2);
            }
            cp_commit();
        }

        // --- O += P(128x64) @ V(64x64) ---
        #pragma unroll
        for (int ks = 0; ks < 4; ks++) {
            const int k = ks * 8;
            uint32_t a[2][4], b0[4], b1[4];
            #pragma unroll
            for (int mi = 0; mi < 2; mi++)
                ldsm4(a[mi], PS_B + ((wm + mi * 16) * 36 + k) * 4 + aoff);
            ldsm4(b0, VT_B + stoff + (wn * 36 + k) * 4 + boff);
            ldsm4(b1, VT_B + stoff + ((wn + 16) * 36 + k) * 4 + boff);
            #pragma unroll
            for (int mi = 0; mi < 2; mi++) {
                mma16(acc_o[mi][0], a[mi], b0);
                mma16(acc_o[mi][1], a[mi], b0 + 2);
                mma16(acc_o[mi][2], a[mi], b1);
                mma16(acc_o[mi][3], a[mi], b1 + 2);
            }
        }
    }

    #pragma unroll
    for (int mi = 0; mi < 2; mi++)
        #pragma unroll
        for (int ni = 0; ni < 4; ni++) {
            int row = b * TT + t0 + wm + mi * 16 + lr;
            int col = wn + ni * 8 + 2 * lc;
            float* o = &out[(size_t)row * HH + col];
            atomicAdd(o,     acc_o[mi][ni][0]);
            atomicAdd(o + 1, acc_o[mi][ni][1]);
            float* o2 = o + 8 * HH;
            atomicAdd(o2,     acc_o[mi][ni][2]);
            atomicAdd(o2 + 1, acc_o[mi][ni][3]);
        }
}

// ---------------------------------------------------------------------------
extern "C" void kernel_launch(void* const* d_in, const int* in_sizes, int n_in,
                              void* d_out, int out_size) {
    const float* x  = (const float*)d_in[0];
    const float* Wq = (const float*)d_in[1];
    const float* Wk = (const float*)d_in[2];
    const float* Wv = (const float*)d_in[3];
    float* out = (float*)d_out;

    const int qkv_smem   = 23040 * 4;           // 92160
    const int stats_smem = 3 * 128 * 36 * 4;    // 55296
    const int pv_smem    = 18432 * 4;           // 73728
    cudaFuncSetAttribute(qkv_kernel,   cudaFuncAttributeMaxDynamicSharedMemorySize, qkv_smem);
    cudaFuncSetAttribute(stats_kernel, cudaFuncAttributeMaxDynamicSharedMemorySize, stats_smem);
    cudaFuncSetAttribute(pv_kernel,    cudaFuncAttributeMaxDynamicSharedMemorySize, pv_smem);

    cudaMemsetAsync(d_out, 0, (size_t)out_size * sizeof(float));
    wconv_kernel<<<72, 256>>>(Wq, Wk, Wv);
    qkv_kernel<<<128, 256, qkv_smem>>>(x);
    stats_kernel<<<dim3(16, 4, BB), 256, stats_smem>>>();
    vscale_kernel<<<2048, 256>>>();
    pv_kernel<<<dim3(8, 16, BB), 256, pv_smem>>>(out);
}